// round 4
// baseline (speedup 1.0000x reference)
#include <cuda_runtime.h>
#include <cstdint>

#define B 8
#define TE 512
#define TD 256
#define H 256
#define HM 200   // h in [0,HM): MUFU tanh; [HM,H): polynomial tanh on fma pipe

typedef unsigned long long ull;
typedef unsigned int uint;

// Scratch (device globals: no allocations allowed)
__device__ float g_WeT[B * H * TE];  // [b][h][i]
__device__ float g_Uh [B * TD * H];  // [b][j][h]

__device__ __forceinline__ float tanh_fast(float x) {
    float y;
    asm("tanh.approx.f32 %0, %1;" : "=f"(y) : "f"(x));
    return y;
}

// ---- packed fp32x2 helpers ----
__device__ __forceinline__ ull pk2(float lo, float hi) {
    ull r; asm("mov.b64 %0, {%1, %2};" : "=l"(r) : "f"(lo), "f"(hi)); return r;
}
__device__ __forceinline__ ull fma2(ull a, ull b, ull c) {
    ull d; asm("fma.rn.f32x2 %0, %1, %2, %3;" : "=l"(d) : "l"(a), "l"(b), "l"(c)); return d;
}
__device__ __forceinline__ ull mul2(ull a, ull b) {
    ull d; asm("mul.rn.f32x2 %0, %1, %2;" : "=l"(d) : "l"(a), "l"(b)); return d;
}
__device__ __forceinline__ ull add2(ull a, ull b) {
    ull d; asm("add.rn.f32x2 %0, %1, %2;" : "=l"(d) : "l"(a), "l"(b)); return d;
}
__device__ __forceinline__ void upk2(ull v, float& lo, float& hi) {
    asm("mov.b64 {%0, %1}, %2;" : "=f"(lo), "=f"(hi) : "l"(v));
}
__device__ __forceinline__ ull dup2(float f) { return pk2(f, f); }

// 4x4 micro-tile step, rows packed in pairs, cols duplicated
__device__ __forceinline__ void micro_fma2(ull acc2[2][4], float4 a, float4 bb) {
    ull pa0 = pk2(a.x, a.y);
    ull pa1 = pk2(a.z, a.w);
    ull pb0 = pk2(bb.x, bb.x);
    ull pb1 = pk2(bb.y, bb.y);
    ull pb2 = pk2(bb.z, bb.z);
    ull pb3 = pk2(bb.w, bb.w);
    acc2[0][0] = fma2(pa0, pb0, acc2[0][0]);
    acc2[0][1] = fma2(pa0, pb1, acc2[0][1]);
    acc2[0][2] = fma2(pa0, pb2, acc2[0][2]);
    acc2[0][3] = fma2(pa0, pb3, acc2[0][3]);
    acc2[1][0] = fma2(pa1, pb0, acc2[1][0]);
    acc2[1][1] = fma2(pa1, pb1, acc2[1][1]);
    acc2[1][2] = fma2(pa1, pb2, acc2[1][2]);
    acc2[1][3] = fma2(pa1, pb3, acc2[1][3]);
}

// ---------------------------------------------------------------------------
// Fused GEMM with GMEM->reg software pipelining.
// blockIdx.x < 8  -> WeT:  g_WeT[b][h][i] = enc[b][i][:] . W[:][h]
// blockIdx.x >= 8 -> Uh :  g_Uh[b][j][h]  = dec[b][j][:] . U[:][h]
// ---------------------------------------------------------------------------
__global__ __launch_bounds__(256) void gemm_fused(const float* __restrict__ enc,
                                                  const float* __restrict__ dec,
                                                  const float* __restrict__ W,
                                                  const float* __restrict__ U) {
    __shared__ float As[16][64];   // [k][row]  (weight, direct)
    __shared__ float Bs[16][68];   // [k][col]  (activation, transposed), padded

    int b = blockIdx.z;
    int t = threadIdx.x;
    int tx = t & 15;
    int ty = t >> 4;

    ull acc2[2][4];
#pragma unroll
    for (int rp = 0; rp < 2; rp++)
#pragma unroll
        for (int c = 0; c < 4; c++) acc2[rp][c] = 0ull;

    bool weT = (blockIdx.x < 8);
    const float* Wm  = weT ? W : U;
    const float* act = weT ? (enc + (size_t)b * TE * H) : (dec + (size_t)b * TD * H);
    int h0 = blockIdx.y * 64;                                // As col block
    int c0 = weT ? blockIdx.x * 64 : (blockIdx.x - 8) * 64;  // Bs col block (i or j)

    int ka = t >> 4, hq = t & 15;       // As loader coords
    int cc = t >> 2, kq = t & 3;        // Bs loader coords

    float4 aReg = *(const float4*)&Wm[ka * H + h0 + hq * 4];
    float4 bReg = *(const float4*)&act[(c0 + cc) * H + kq * 4];

#pragma unroll 1
    for (int kt = 0; kt < 16; kt++) {
        *(float4*)&As[ka][hq * 4] = aReg;
        Bs[kq * 4 + 0][cc] = bReg.x;
        Bs[kq * 4 + 1][cc] = bReg.y;
        Bs[kq * 4 + 2][cc] = bReg.z;
        Bs[kq * 4 + 3][cc] = bReg.w;
        __syncthreads();
        if (kt < 15) {
            int k0 = (kt + 1) * 16;
            aReg = *(const float4*)&Wm[(k0 + ka) * H + h0 + hq * 4];
            bReg = *(const float4*)&act[(c0 + cc) * H + k0 + kq * 4];
        }
#pragma unroll
        for (int kk = 0; kk < 16; kk++) {
            // rows ALWAYS indexed by ty, cols ALWAYS by tx (R3 bug: swapped operands
            // without swapping indices). WeT: rows=h from As. Uh: rows=j from Bs.
            float4 a, bb;
            if (weT) { a = *(float4*)&As[kk][ty * 4]; bb = *(float4*)&Bs[kk][tx * 4]; }
            else     { a = *(float4*)&Bs[kk][ty * 4]; bb = *(float4*)&As[kk][tx * 4]; }
            micro_fma2(acc2, a, bb);
        }
        __syncthreads();
    }

    float o[4][4];
#pragma unroll
    for (int rp = 0; rp < 2; rp++)
#pragma unroll
        for (int c = 0; c < 4; c++)
            upk2(acc2[rp][c], o[2 * rp][c], o[2 * rp + 1][c]);

    if (weT) {
        float* out = g_WeT + (size_t)b * H * TE;
#pragma unroll
        for (int r = 0; r < 4; r++) {
            float4 v = make_float4(o[r][0], o[r][1], o[r][2], o[r][3]);
            *(float4*)&out[(h0 + ty * 4 + r) * TE + c0 + tx * 4] = v;
        }
    } else {
        float* out = g_Uh + (size_t)b * TD * H;
#pragma unroll
        for (int r = 0; r < 4; r++) {
            float4 v = make_float4(o[r][0], o[r][1], o[r][2], o[r][3]);
            *(float4*)&out[(c0 + ty * 4 + r) * H + h0 + tx * 4] = v;
        }
    }
}

// ---------------------------------------------------------------------------
// Energy + softmax, hybrid tanh. One block per (b, 2 decoder rows) -> 1024 blocks.
// 512 threads, thread = encoder position i.
// ---------------------------------------------------------------------------
__global__ __launch_bounds__(512, 2) void energy_kernel(const float* __restrict__ Va,
                                                        float* __restrict__ e_out) {
    __shared__ float Us2[2 * H];   // interleaved (u_j0[h], u_j1[h])
    __shared__ float Vs2[2 * H];   // duplicated  (v[h], v[h])
    __shared__ float red[16][2];
    __shared__ float bmax[2];
    __shared__ float binv[2];

    int t  = threadIdx.x;
    int b  = blockIdx.x >> 7;
    int j0 = (blockIdx.x & 127) * 2;

    if (t < H) {
        Us2[2 * t] = g_Uh[((size_t)b * TD + j0) * H + t];
        float v = Va[t];
        Vs2[2 * t] = v; Vs2[2 * t + 1] = v;
    } else {
        int h = t - H;
        Us2[2 * h + 1] = g_Uh[((size_t)b * TD + j0 + 1) * H + h];
    }
    __syncthreads();

    const int i = t;
    const float* wp = g_WeT + (size_t)b * H * TE + i;

    float acc0 = 0.f, acc1 = 0.f;

    // ---- MUFU region ----
#pragma unroll 8
    for (int h = 0; h < HM; h++) {
        float w = wp[h * TE];
        ull u = *(const ull*)&Us2[2 * h];
        ull x = add2(pk2(w, w), u);
        float x0, x1; upk2(x, x0, x1);
        float v = Vs2[2 * h];
        acc0 = fmaf(v, tanh_fast(x0), acc0);
        acc1 = fmaf(v, tanh_fast(x1), acc1);
    }

    // ---- polynomial region (Eigen fast-tanh rational 13/6, packed f32x2) ----
    const ull ca13 = dup2(-2.76076847742355e-16f);
    const ull ca11 = dup2( 2.00018790482477e-13f);
    const ull ca9  = dup2(-8.60467152213735e-11f);
    const ull ca7  = dup2( 5.12229709037114e-08f);
    const ull ca5  = dup2( 1.48572235717979e-05f);
    const ull ca3  = dup2( 6.37261928875436e-04f);
    const ull ca1  = dup2( 4.89352455891786e-03f);
    const ull cb6  = dup2( 1.19825839466702e-06f);
    const ull cb4  = dup2( 1.18534705686654e-04f);
    const ull cb2  = dup2( 2.26843463243900e-03f);
    const ull cb0  = dup2( 4.89352518554385e-03f);
    const ull ctwo = dup2(2.0f);
    const ull cneg1 = dup2(-1.0f);
    const float CL = 7.90531110763549805f;   // Eigen's validated clamp

    ull accp = 0ull;
#pragma unroll 2
    for (int h = HM; h < H; h++) {
        float w = wp[h * TE];
        ull u = *(const ull*)&Us2[2 * h];
        float x0, x1; upk2(add2(pk2(w, w), u), x0, x1);
        x0 = fminf(fmaxf(x0, -CL), CL);
        x1 = fminf(fmaxf(x1, -CL), CL);
        ull x  = pk2(x0, x1);
        ull x2 = mul2(x, x);
        ull A = fma2(ca13, x2, ca11);
        A = fma2(A, x2, ca9);
        A = fma2(A, x2, ca7);
        A = fma2(A, x2, ca5);
        A = fma2(A, x2, ca3);
        A = fma2(A, x2, ca1);
        A = mul2(A, x);
        ull Bt = fma2(cb6, x2, cb4);
        Bt = fma2(Bt, x2, cb2);
        Bt = fma2(Bt, x2, cb0);       // Bt > 0 always
        // fast reciprocal: magic init + 2 Newton (no MUFU)
        uint blo = (uint)Bt, bhi = (uint)(Bt >> 32);
        blo = 0x7EF127EAu - blo;
        bhi = 0x7EF127EAu - bhi;
        ull r  = ((ull)bhi << 32) | (ull)blo;
        ull nb = mul2(Bt, cneg1);
        r = mul2(r, fma2(nb, r, ctwo));
        r = mul2(r, fma2(nb, r, ctwo));
        ull vv = *(const ull*)&Vs2[2 * h];
        ull Av = mul2(A, vv);
        accp = fma2(Av, r, accp);     // acc += v * (A/Bt)
    }
    { float p0, p1; upk2(accp, p0, p1); acc0 += p0; acc1 += p1; }

    // ---- softmax over i ----
    int lane = t & 31, wrp = t >> 5;
    float m0 = acc0, m1 = acc1;
#pragma unroll
    for (int o = 16; o; o >>= 1) {
        m0 = fmaxf(m0, __shfl_xor_sync(0xffffffffu, m0, o));
        m1 = fmaxf(m1, __shfl_xor_sync(0xffffffffu, m1, o));
    }
    if (lane == 0) { red[wrp][0] = m0; red[wrp][1] = m1; }
    __syncthreads();
    if (t < 2) {
        float m = red[0][t];
#pragma unroll
        for (int w2 = 1; w2 < 16; w2++) m = fmaxf(m, red[w2][t]);
        bmax[t] = m;
    }
    __syncthreads();

    float p0 = __expf(acc0 - bmax[0]);
    float p1 = __expf(acc1 - bmax[1]);
    float s0 = p0, s1 = p1;
#pragma unroll
    for (int o = 16; o; o >>= 1) {
        s0 += __shfl_xor_sync(0xffffffffu, s0, o);
        s1 += __shfl_xor_sync(0xffffffffu, s1, o);
    }
    if (lane == 0) { red[wrp][0] = s0; red[wrp][1] = s1; }
    __syncthreads();
    if (t < 2) {
        float s = 0.f;
#pragma unroll
        for (int w2 = 0; w2 < 16; w2++) s += red[w2][t];
        binv[t] = 1.0f / s;
    }
    __syncthreads();

    float* e0 = e_out + ((size_t)b * TD + j0) * TE;
    e0[i]      = p0 * binv[0];
    e0[TE + i] = p1 * binv[1];
}

// ---------------------------------------------------------------------------
// Context GEMM with prefetch: c[b] = P[b] @ enc[b]   ([TD x TE] x [TE x H])
// ---------------------------------------------------------------------------
__global__ __launch_bounds__(256) void ctx_gemm(const float* __restrict__ P,
                                                const float* __restrict__ enc,
                                                float* __restrict__ c_out) {
    __shared__ float As[16][68];   // [k][j] transposed from P, padded
    __shared__ float Bs[16][64];   // [k][h] direct from enc

    int b  = blockIdx.z;
    int j0 = blockIdx.y * 64;
    int h0 = blockIdx.x * 64;
    int t  = threadIdx.x;
    int tx = t & 15;
    int ty = t >> 4;

    ull acc2[2][4];
#pragma unroll
    for (int rp = 0; rp < 2; rp++)
#pragma unroll
        for (int c = 0; c < 4; c++) acc2[rp][c] = 0ull;

    const float* Pb = P   + (size_t)b * TD * TE;
    const float* eb = enc + (size_t)b * TE * H;

    int jj = t >> 2, kq = t & 3;
    int kb = t >> 4, hq = t & 15;

    float4 aReg = *(const float4*)&Pb[(j0 + jj) * TE + kq * 4];
    float4 bReg = *(const float4*)&eb[kb * H + h0 + hq * 4];

#pragma unroll 1
    for (int kt = 0; kt < 32; kt++) {
        As[kq * 4 + 0][jj] = aReg.x;
        As[kq * 4 + 1][jj] = aReg.y;
        As[kq * 4 + 2][jj] = aReg.z;
        As[kq * 4 + 3][jj] = aReg.w;
        *(float4*)&Bs[kb][hq * 4] = bReg;
        __syncthreads();
        if (kt < 31) {
            int k0 = (kt + 1) * 16;
            aReg = *(const float4*)&Pb[(j0 + jj) * TE + k0 + kq * 4];
            bReg = *(const float4*)&eb[(k0 + kb) * H + h0 + hq * 4];
        }
#pragma unroll
        for (int kk = 0; kk < 16; kk++) {
            float4 a  = *(float4*)&As[kk][ty * 4];   // rows j (pairs)
            float4 bb = *(float4*)&Bs[kk][tx * 4];   // cols h (dup)
            micro_fma2(acc2, a, bb);
        }
        __syncthreads();
    }

    float o[4][4];
#pragma unroll
    for (int rp = 0; rp < 2; rp++)
#pragma unroll
        for (int c = 0; c < 4; c++)
            upk2(acc2[rp][c], o[2 * rp][c], o[2 * rp + 1][c]);

#pragma unroll
    for (int r = 0; r < 4; r++) {
        float4 v = make_float4(o[r][0], o[r][1], o[r][2], o[r][3]);
        *(float4*)&c_out[((size_t)b * TD + j0 + ty * 4 + r) * H + h0 + tx * 4] = v;
    }
}

// ---------------------------------------------------------------------------
extern "C" void kernel_launch(void* const* d_in, const int* in_sizes, int n_in,
                              void* d_out, int out_size) {
    const float* enc = (const float*)d_in[0];  // [B,TE,H]
    const float* dec = (const float*)d_in[1];  // [B,TD,H]
    const float* W   = (const float*)d_in[2];  // [H,H]
    const float* U   = (const float*)d_in[3];  // [H,H]
    const float* V   = (const float*)d_in[4];  // [H,1]

    float* c_out = (float*)d_out;              // [B,TD,H]
    float* e_out = (float*)d_out + B * TD * H; // [B,TD,TE]

    dim3 gg(12, 4, B);
    gemm_fused<<<gg, 256>>>(enc, dec, W, U);
    energy_kernel<<<B * (TD / 2), 512>>>(V, e_out);
    dim3 gc(H / 64, TD / 64, B);
    ctx_gemm<<<gc, 256>>>(e_out, enc, c_out);
}

// round 5
// speedup vs baseline: 1.1517x; 1.1517x over previous
#include <cuda_runtime.h>
#include <cstdint>

#define B 8
#define TE 512
#define TD 256
#define H 256

typedef unsigned long long ull;

// Scratch (device globals: no allocations allowed)
__device__ float g_WeT[B * H * TE];  // [b][h][i]
__device__ float g_Uh [B * TD * H];  // [b][j][h]

__device__ __forceinline__ float tanh_fast(float x) {
    float y;
    asm("tanh.approx.f32 %0, %1;" : "=f"(y) : "f"(x));
    return y;
}

// ---- packed fp32x2 helpers ----
__device__ __forceinline__ ull pk2(float lo, float hi) {
    ull r; asm("mov.b64 %0, {%1, %2};" : "=l"(r) : "f"(lo), "f"(hi)); return r;
}
__device__ __forceinline__ ull fma2(ull a, ull b, ull c) {
    ull d; asm("fma.rn.f32x2 %0, %1, %2, %3;" : "=l"(d) : "l"(a), "l"(b), "l"(c)); return d;
}
__device__ __forceinline__ void upk2(ull v, float& lo, float& hi) {
    asm("mov.b64 {%0, %1}, %2;" : "=f"(lo), "=f"(hi) : "l"(v));
}

// 4x4 micro-tile step, rows packed in pairs, cols duplicated
__device__ __forceinline__ void micro_fma2(ull acc2[2][4], float4 a, float4 bb) {
    ull pa0 = pk2(a.x, a.y);
    ull pa1 = pk2(a.z, a.w);
    ull pb0 = pk2(bb.x, bb.x);
    ull pb1 = pk2(bb.y, bb.y);
    ull pb2 = pk2(bb.z, bb.z);
    ull pb3 = pk2(bb.w, bb.w);
    acc2[0][0] = fma2(pa0, pb0, acc2[0][0]);
    acc2[0][1] = fma2(pa0, pb1, acc2[0][1]);
    acc2[0][2] = fma2(pa0, pb2, acc2[0][2]);
    acc2[0][3] = fma2(pa0, pb3, acc2[0][3]);
    acc2[1][0] = fma2(pa1, pb0, acc2[1][0]);
    acc2[1][1] = fma2(pa1, pb1, acc2[1][1]);
    acc2[1][2] = fma2(pa1, pb2, acc2[1][2]);
    acc2[1][3] = fma2(pa1, pb3, acc2[1][3]);
}

// ---------------------------------------------------------------------------
// Fused GEMM, double-buffered smem pipeline, branch fully hoisted.
// blockIdx.x < 8  -> WeT:  g_WeT[b][h][i] = enc[b][i][:] . W[:][h]
// blockIdx.x >= 8 -> Uh :  g_Uh[b][j][h]  = dec[b][j][:] . U[:][h]
// ---------------------------------------------------------------------------
__global__ __launch_bounds__(256) void gemm_fused(const float* __restrict__ enc,
                                                  const float* __restrict__ dec,
                                                  const float* __restrict__ W,
                                                  const float* __restrict__ U) {
    __shared__ float As[2][16][64];   // [buf][k][row]  (weight, direct)
    __shared__ float Bs[2][16][68];   // [buf][k][col]  (activation, transposed)

    int b = blockIdx.z;
    int t = threadIdx.x;
    int tx = t & 15;
    int ty = t >> 4;

    ull acc2[2][4];
#pragma unroll
    for (int rp = 0; rp < 2; rp++)
#pragma unroll
        for (int c = 0; c < 4; c++) acc2[rp][c] = 0ull;

    bool weT = (blockIdx.x < 8);
    const float* Wm  = weT ? W : U;
    const float* act = weT ? (enc + (size_t)b * TE * H) : (dec + (size_t)b * TD * H);
    int h0 = blockIdx.y * 64;                                // As col block
    int c0 = weT ? blockIdx.x * 64 : (blockIdx.x - 8) * 64;  // Bs col block (i or j)

    int ka = t >> 4, hq = t & 15;       // As loader coords
    int cc = t >> 2, kq = t & 3;        // Bs loader coords

    // stage tile 0 into buffer 0
    {
        float4 aReg = *(const float4*)&Wm[ka * H + h0 + hq * 4];
        float4 bReg = *(const float4*)&act[(c0 + cc) * H + kq * 4];
        *(float4*)&As[0][ka][hq * 4] = aReg;
        Bs[0][kq * 4 + 0][cc] = bReg.x;
        Bs[0][kq * 4 + 1][cc] = bReg.y;
        Bs[0][kq * 4 + 2][cc] = bReg.z;
        Bs[0][kq * 4 + 3][cc] = bReg.w;
    }
    __syncthreads();

    if (weT) {
#pragma unroll 1
        for (int kt = 0; kt < 16; kt++) {
            int cur = kt & 1;
            float4 aReg, bReg;
            if (kt < 15) {
                int k0 = (kt + 1) * 16;
                aReg = *(const float4*)&Wm[(k0 + ka) * H + h0 + hq * 4];
                bReg = *(const float4*)&act[(c0 + cc) * H + k0 + kq * 4];
            }
#pragma unroll
            for (int kk = 0; kk < 16; kk++) {
                float4 a  = *(float4*)&As[cur][kk][ty * 4];   // rows = h
                float4 bb = *(float4*)&Bs[cur][kk][tx * 4];   // cols = i
                micro_fma2(acc2, a, bb);
            }
            if (kt < 15) {
                int nxt = cur ^ 1;
                *(float4*)&As[nxt][ka][hq * 4] = aReg;
                Bs[nxt][kq * 4 + 0][cc] = bReg.x;
                Bs[nxt][kq * 4 + 1][cc] = bReg.y;
                Bs[nxt][kq * 4 + 2][cc] = bReg.z;
                Bs[nxt][kq * 4 + 3][cc] = bReg.w;
                __syncthreads();
            }
        }
        float o[4][4];
#pragma unroll
        for (int rp = 0; rp < 2; rp++)
#pragma unroll
            for (int c = 0; c < 4; c++)
                upk2(acc2[rp][c], o[2 * rp][c], o[2 * rp + 1][c]);
        float* out = g_WeT + (size_t)b * H * TE;
#pragma unroll
        for (int r = 0; r < 4; r++) {
            float4 v = make_float4(o[r][0], o[r][1], o[r][2], o[r][3]);
            *(float4*)&out[(h0 + ty * 4 + r) * TE + c0 + tx * 4] = v;
        }
    } else {
#pragma unroll 1
        for (int kt = 0; kt < 16; kt++) {
            int cur = kt & 1;
            float4 aReg, bReg;
            if (kt < 15) {
                int k0 = (kt + 1) * 16;
                aReg = *(const float4*)&Wm[(k0 + ka) * H + h0 + hq * 4];
                bReg = *(const float4*)&act[(c0 + cc) * H + k0 + kq * 4];
            }
#pragma unroll
            for (int kk = 0; kk < 16; kk++) {
                float4 a  = *(float4*)&Bs[cur][kk][ty * 4];   // rows = j
                float4 bb = *(float4*)&As[cur][kk][tx * 4];   // cols = h
                micro_fma2(acc2, a, bb);
            }
            if (kt < 15) {
                int nxt = cur ^ 1;
                *(float4*)&As[nxt][ka][hq * 4] = aReg;
                Bs[nxt][kq * 4 + 0][cc] = bReg.x;
                Bs[nxt][kq * 4 + 1][cc] = bReg.y;
                Bs[nxt][kq * 4 + 2][cc] = bReg.z;
                Bs[nxt][kq * 4 + 3][cc] = bReg.w;
                __syncthreads();
            }
        }
        float o[4][4];
#pragma unroll
        for (int rp = 0; rp < 2; rp++)
#pragma unroll
            for (int c = 0; c < 4; c++)
                upk2(acc2[rp][c], o[2 * rp][c], o[2 * rp + 1][c]);
        float* out = g_Uh + (size_t)b * TD * H;
#pragma unroll
        for (int r = 0; r < 4; r++) {
            float4 v = make_float4(o[r][0], o[r][1], o[r][2], o[r][3]);
            *(float4*)&out[(c0 + ty * 4 + r) * H + h0 + tx * 4] = v;
        }
    }
}

// ---------------------------------------------------------------------------
// Energy + softmax, pure MUFU, JT=4. One block per (b, 4 decoder rows) -> 512
// blocks, 512 threads, thread = encoder position i.
// Uh tile stored interleaved [h][jj] so one LDS.128 serves 4 j's.
// No max-subtraction: |energy| <= sum|V| <= 12.8, expf cannot overflow.
// ---------------------------------------------------------------------------
__global__ __launch_bounds__(512) void energy_kernel(const float* __restrict__ Va,
                                                     float* __restrict__ e_out) {
    __shared__ float Us4[H * 4];     // [h][jj]
    __shared__ float Vs[H];
    __shared__ float red[16][4];
    __shared__ float binv[4];

    int t  = threadIdx.x;
    int b  = blockIdx.x >> 6;            // TD/4 = 64 tiles per batch
    int j0 = (blockIdx.x & 63) * 4;

    for (int idx = t; idx < 4 * H; idx += 512) {
        int jj = idx >> 8;               // 0..3
        int h  = idx & (H - 1);
        Us4[h * 4 + jj] = g_Uh[((size_t)b * TD + j0 + jj) * H + h];
    }
    if (t < H) Vs[t] = Va[t];
    __syncthreads();

    const int i = t;
    const float* wp = g_WeT + (size_t)b * H * TE + i;

    float acc0 = 0.f, acc1 = 0.f, acc2 = 0.f, acc3 = 0.f;
#pragma unroll 4
    for (int h = 0; h < H; h++) {
        float w = wp[h * TE];
        float4 u = *(const float4*)&Us4[h * 4];
        float v = Vs[h];
        acc0 = fmaf(v, tanh_fast(w + u.x), acc0);
        acc1 = fmaf(v, tanh_fast(w + u.y), acc1);
        acc2 = fmaf(v, tanh_fast(w + u.z), acc2);
        acc3 = fmaf(v, tanh_fast(w + u.w), acc3);
    }

    // ---- softmax over i (no max subtraction; energies bounded) ----
    float p0 = __expf(acc0);
    float p1 = __expf(acc1);
    float p2 = __expf(acc2);
    float p3 = __expf(acc3);

    int lane = t & 31, wrp = t >> 5;
    float s0 = p0, s1 = p1, s2 = p2, s3 = p3;
#pragma unroll
    for (int o = 16; o; o >>= 1) {
        s0 += __shfl_xor_sync(0xffffffffu, s0, o);
        s1 += __shfl_xor_sync(0xffffffffu, s1, o);
        s2 += __shfl_xor_sync(0xffffffffu, s2, o);
        s3 += __shfl_xor_sync(0xffffffffu, s3, o);
    }
    if (lane == 0) { red[wrp][0] = s0; red[wrp][1] = s1; red[wrp][2] = s2; red[wrp][3] = s3; }
    __syncthreads();
    if (t < 4) {
        float s = 0.f;
#pragma unroll
        for (int w2 = 0; w2 < 16; w2++) s += red[w2][t];
        binv[t] = 1.0f / s;
    }
    __syncthreads();

    float* e0 = e_out + ((size_t)b * TD + j0) * TE;
    e0[0 * TE + i] = p0 * binv[0];
    e0[1 * TE + i] = p1 * binv[1];
    e0[2 * TE + i] = p2 * binv[2];
    e0[3 * TE + i] = p3 * binv[3];
}

// ---------------------------------------------------------------------------
// Context GEMM, double-buffered: c[b] = P[b] @ enc[b]   ([TD x TE] x [TE x H])
// ---------------------------------------------------------------------------
__global__ __launch_bounds__(256) void ctx_gemm(const float* __restrict__ P,
                                                const float* __restrict__ enc,
                                                float* __restrict__ c_out) {
    __shared__ float As[2][16][68];   // [buf][k][j] transposed from P
    __shared__ float Bs[2][16][64];   // [buf][k][h] direct from enc

    int b  = blockIdx.z;
    int j0 = blockIdx.y * 64;
    int h0 = blockIdx.x * 64;
    int t  = threadIdx.x;
    int tx = t & 15;
    int ty = t >> 4;

    ull acc2[2][4];
#pragma unroll
    for (int rp = 0; rp < 2; rp++)
#pragma unroll
        for (int c = 0; c < 4; c++) acc2[rp][c] = 0ull;

    const float* Pb = P   + (size_t)b * TD * TE;
    const float* eb = enc + (size_t)b * TE * H;

    int jj = t >> 2, kq = t & 3;
    int kb = t >> 4, hq = t & 15;

    {
        float4 aReg = *(const float4*)&Pb[(j0 + jj) * TE + kq * 4];
        float4 bReg = *(const float4*)&eb[kb * H + h0 + hq * 4];
        As[0][kq * 4 + 0][jj] = aReg.x;
        As[0][kq * 4 + 1][jj] = aReg.y;
        As[0][kq * 4 + 2][jj] = aReg.z;
        As[0][kq * 4 + 3][jj] = aReg.w;
        *(float4*)&Bs[0][kb][hq * 4] = bReg;
    }
    __syncthreads();

#pragma unroll 1
    for (int kt = 0; kt < 32; kt++) {
        int cur = kt & 1;
        float4 aReg, bReg;
        if (kt < 31) {
            int k0 = (kt + 1) * 16;
            aReg = *(const float4*)&Pb[(j0 + jj) * TE + k0 + kq * 4];
            bReg = *(const float4*)&eb[(k0 + kb) * H + h0 + hq * 4];
        }
#pragma unroll
        for (int kk = 0; kk < 16; kk++) {
            float4 a  = *(float4*)&As[cur][kk][ty * 4];   // rows j (pairs)
            float4 bb = *(float4*)&Bs[cur][kk][tx * 4];   // cols h (dup)
            micro_fma2(acc2, a, bb);
        }
        if (kt < 31) {
            int nxt = cur ^ 1;
            As[nxt][kq * 4 + 0][jj] = aReg.x;
            As[nxt][kq * 4 + 1][jj] = aReg.y;
            As[nxt][kq * 4 + 2][jj] = aReg.z;
            As[nxt][kq * 4 + 3][jj] = aReg.w;
            *(float4*)&Bs[nxt][kb][hq * 4] = bReg;
            __syncthreads();
        }
    }

    float o[4][4];
#pragma unroll
    for (int rp = 0; rp < 2; rp++)
#pragma unroll
        for (int c = 0; c < 4; c++)
            upk2(acc2[rp][c], o[2 * rp][c], o[2 * rp + 1][c]);

#pragma unroll
    for (int r = 0; r < 4; r++) {
        float4 v = make_float4(o[r][0], o[r][1], o[r][2], o[r][3]);
        *(float4*)&c_out[((size_t)b * TD + j0 + ty * 4 + r) * H + h0 + tx * 4] = v;
    }
}

// ---------------------------------------------------------------------------
extern "C" void kernel_launch(void* const* d_in, const int* in_sizes, int n_in,
                              void* d_out, int out_size) {
    const float* enc = (const float*)d_in[0];  // [B,TE,H]
    const float* dec = (const float*)d_in[1];  // [B,TD,H]
    const float* W   = (const float*)d_in[2];  // [H,H]
    const float* U   = (const float*)d_in[3];  // [H,H]
    const float* V   = (const float*)d_in[4];  // [H,1]

    float* c_out = (float*)d_out;              // [B,TD,H]
    float* e_out = (float*)d_out + B * TD * H; // [B,TD,TE]

    dim3 gg(12, 4, B);
    gemm_fused<<<gg, 256>>>(enc, dec, W, U);
    energy_kernel<<<B * (TD / 4), 512>>>(V, e_out);
    dim3 gc(H / 64, TD / 64, B);
    ctx_gemm<<<gc, 256>>>(e_out, enc, c_out);
}